// round 10
// baseline (speedup 1.0000x reference)
#include <cuda_runtime.h>
#include <cuda_bf16.h>
#include <cstdint>
#include <math.h>

#define BATCH 8
#define SEQ   2048
#define DA    768
#define DB    1024

// ---------------- scratch (device globals; module-load allocation) ---------
__device__ float g_s   [BATCH * SEQ * SEQ];            // fp32 scores
__device__ float g_xb2 [BATCH * SEQ * DB];             // fp32 residual
// bf16 hi/lo pairs
__device__ __nv_bfloat16 g_xbh[BATCH * SEQ * DB],  g_xbl[BATCH * SEQ * DB];
__device__ __nv_bfloat16 g_xah[BATCH * SEQ * DA],  g_xal[BATCH * SEQ * DA];
__device__ __nv_bfloat16 g_qh [BATCH * SEQ * DB],  g_ql [BATCH * SEQ * DB];
__device__ __nv_bfloat16 g_kh [BATCH * SEQ * DB],  g_kl [BATCH * SEQ * DB];
__device__ __nv_bfloat16 g_vh [BATCH * SEQ * DB],  g_vl [BATCH * SEQ * DB];
__device__ __nv_bfloat16 g_vth[BATCH * SEQ * DB],  g_vtl[BATCH * SEQ * DB];
__device__ __nv_bfloat16 g_ph [BATCH * SEQ * SEQ], g_pl [BATCH * SEQ * SEQ];
__device__ __nv_bfloat16 g_x2h[BATCH * SEQ * DB],  g_x2l[BATCH * SEQ * DB];
__device__ __nv_bfloat16 g_ath[BATCH * SEQ * DB],  g_atl[BATCH * SEQ * DB];
__device__ __nv_bfloat16 g_wth[8 * DB * DB],       g_wtl[8 * DB * DB];

// ---------------- helpers ---------------------------------------------------
__device__ __forceinline__ void split_bf16(float x, __nv_bfloat16& h, __nv_bfloat16& l) {
    h = __float2bfloat16_rn(x);
    l = __float2bfloat16_rn(x - __bfloat162float(h));
}
__device__ __forceinline__ uint32_t pack2(__nv_bfloat16 a, __nv_bfloat16 b) {
    __nv_bfloat162 t; t.x = a; t.y = b;
    return *(uint32_t*)&t;
}

#define MMA_BF16(acc, Af, Bf)                                                  \
    asm volatile(                                                              \
        "mma.sync.aligned.m16n8k16.row.col.f32.bf16.bf16.f32 "                 \
        "{%0,%1,%2,%3},{%4,%5,%6,%7},{%8,%9},{%0,%1,%2,%3};"                   \
        : "+f"((acc)[0]), "+f"((acc)[1]), "+f"((acc)[2]), "+f"((acc)[3])       \
        : "r"((Af)[0]), "r"((Af)[1]), "r"((Af)[2]), "r"((Af)[3]),              \
          "r"((Bf)[0]), "r"((Bf)[1]))

// ---------------------------------------------------------------------------
// mma.sync GEMM on pre-split bf16 operands (3-pass hi/lo compensation):
//   C = alpha * A @ B^T [+ bias] [+ res];  A:[M,K], B:[N,K], both as (h,l).
//   CTA 128x128, K-chunk 32, 8 warps as 2(M)x4(N), warp tile 64x32, m16n8k16.
//   Epilogue writes fp32 C and/or split bf16 (Ch, Cl).
// ---------------------------------------------------------------------------
#define KSTR 20              // smem row stride in b32 (40 bf16: 32 data + 8 pad)
#define ARR_B32 (128 * KSTR)

template<bool HAS_BIAS, bool HAS_RES, bool WRITE_F32, bool WRITE_SPLIT>
__global__ __launch_bounds__(256)
void mma_gemm(const __nv_bfloat16* __restrict__ Ah, const __nv_bfloat16* __restrict__ Al,
              const __nv_bfloat16* __restrict__ Bh, const __nv_bfloat16* __restrict__ Bl,
              const float* __restrict__ bias, const float* __restrict__ res,
              float* __restrict__ C, __nv_bfloat16* __restrict__ Ch,
              __nv_bfloat16* __restrict__ Cl,
              int M, int N, int K, float alpha,
              size_t sA, size_t sB, size_t sC)
{
    __shared__ uint32_t sm[4 * ARR_B32];   // 40 KB static
    uint32_t* ah32 = sm;
    uint32_t* al32 = sm + ARR_B32;
    uint32_t* bh32 = sm + 2 * ARR_B32;
    uint32_t* bl32 = sm + 3 * ARR_B32;

    const int bz = blockIdx.z;
    Ah += (size_t)bz * sA; Al += (size_t)bz * sA;
    Bh += (size_t)bz * sB; Bl += (size_t)bz * sB;
    const size_t cOff = (size_t)bz * sC;

    const int row0 = blockIdx.y * 128;
    const int col0 = blockIdx.x * 128;
    const int tid  = threadIdx.x;
    const int wid  = tid >> 5;
    const int lane = tid & 31;
    const int wm   = wid >> 2;          // 0..1  (M)
    const int wn   = wid & 3;           // 0..3  (N)
    const int lr   = lane >> 2;         // 0..7
    const int lc   = lane & 3;          // 0..3

    float acc[4][4][4];
    #pragma unroll
    for (int a = 0; a < 4; a++)
        #pragma unroll
        for (int b = 0; b < 4; b++)
            #pragma unroll
            for (int c = 0; c < 4; c++)
                acc[a][b][c] = 0.0f;

    const int nCh = K / 32;
    uint4 gah[2], gal[2], gbh[2], gbl[2];

    // prologue: stage 0 into registers (each thread: 2 x 16B per array)
    #pragma unroll
    for (int i = 0; i < 2; i++) {
        int f = tid + i * 256, r = f >> 2, c = f & 3;    // r:0..127, c:16B unit
        size_t oa = (size_t)(row0 + r) * K + c * 8;
        size_t ob = (size_t)(col0 + r) * K + c * 8;
        gah[i] = *(const uint4*)&Ah[oa]; gal[i] = *(const uint4*)&Al[oa];
        gbh[i] = *(const uint4*)&Bh[ob]; gbl[i] = *(const uint4*)&Bl[ob];
    }

    for (int ch = 0; ch < nCh; ch++) {
        #pragma unroll
        for (int i = 0; i < 2; i++) {
            int f = tid + i * 256, r = f >> 2, c = f & 3;
            int o = r * KSTR + c * 4;                    // b32 index, 16B aligned
            *(uint4*)&ah32[o] = gah[i]; *(uint4*)&al32[o] = gal[i];
            *(uint4*)&bh32[o] = gbh[i]; *(uint4*)&bl32[o] = gbl[i];
        }
        __syncthreads();

        if (ch + 1 < nCh) {
            const int kb = (ch + 1) * 32;
            #pragma unroll
            for (int i = 0; i < 2; i++) {
                int f = tid + i * 256, r = f >> 2, c = f & 3;
                size_t oa = (size_t)(row0 + r) * K + kb + c * 8;
                size_t ob = (size_t)(col0 + r) * K + kb + c * 8;
                gah[i] = *(const uint4*)&Ah[oa]; gal[i] = *(const uint4*)&Al[oa];
                gbh[i] = *(const uint4*)&Bh[ob]; gbl[i] = *(const uint4*)&Bl[ob];
            }
        }

        #pragma unroll
        for (int s = 0; s < 2; s++) {
            const int kp = s * 8 + lc;
            uint32_t Afh[4][4], Afl[4][4], Bfh[4][2], Bfl[4][2];
            #pragma unroll
            for (int mt = 0; mt < 4; mt++) {
                int r = wm * 64 + mt * 16 + lr;
                int i0 = r * KSTR + kp, i1 = (r + 8) * KSTR + kp;
                Afh[mt][0] = ah32[i0];     Afh[mt][1] = ah32[i1];
                Afh[mt][2] = ah32[i0 + 4]; Afh[mt][3] = ah32[i1 + 4];
                Afl[mt][0] = al32[i0];     Afl[mt][1] = al32[i1];
                Afl[mt][2] = al32[i0 + 4]; Afl[mt][3] = al32[i1 + 4];
            }
            #pragma unroll
            for (int nt = 0; nt < 4; nt++) {
                int n = wn * 32 + nt * 8 + lr;
                int i0 = n * KSTR + kp;
                Bfh[nt][0] = bh32[i0]; Bfh[nt][1] = bh32[i0 + 4];
                Bfl[nt][0] = bl32[i0]; Bfl[nt][1] = bl32[i0 + 4];
            }
            #pragma unroll
            for (int mt = 0; mt < 4; mt++)
                #pragma unroll
                for (int nt = 0; nt < 4; nt++) {
                    MMA_BF16(acc[mt][nt], Afh[mt], Bfh[nt]);
                    MMA_BF16(acc[mt][nt], Afh[mt], Bfl[nt]);
                    MMA_BF16(acc[mt][nt], Afl[mt], Bfh[nt]);
                }
        }
        __syncthreads();
    }

    // ---- epilogue ----
    const float* __restrict__ R = HAS_RES ? (res + cOff) : nullptr;
    #pragma unroll
    for (int mt = 0; mt < 4; mt++) {
        #pragma unroll
        for (int nt = 0; nt < 4; nt++) {
            int r = row0 + wm * 64 + mt * 16 + lr;
            int c = col0 + wn * 32 + nt * 8 + lc * 2;
            float2 o0, o1;
            o0.x = acc[mt][nt][0] * alpha; o0.y = acc[mt][nt][1] * alpha;
            o1.x = acc[mt][nt][2] * alpha; o1.y = acc[mt][nt][3] * alpha;
            if (HAS_BIAS) {
                float2 bv = *(const float2*)&bias[c];
                o0.x += bv.x; o0.y += bv.y;
                o1.x += bv.x; o1.y += bv.y;
            }
            if (HAS_RES) {
                float2 r0 = *(const float2*)&R[(size_t)r * N + c];
                float2 r1 = *(const float2*)&R[(size_t)(r + 8) * N + c];
                o0.x += r0.x; o0.y += r0.y;
                o1.x += r1.x; o1.y += r1.y;
            }
            if (WRITE_F32) {
                *(float2*)&C[cOff + (size_t)r * N + c]       = o0;
                *(float2*)&C[cOff + (size_t)(r + 8) * N + c] = o1;
            }
            if (WRITE_SPLIT) {
                __nv_bfloat16 hx, lx, hy, ly;
                split_bf16(o0.x, hx, lx); split_bf16(o0.y, hy, ly);
                *(uint32_t*)&Ch[cOff + (size_t)r * N + c] = pack2(hx, hy);
                *(uint32_t*)&Cl[cOff + (size_t)r * N + c] = pack2(lx, ly);
                split_bf16(o1.x, hx, lx); split_bf16(o1.y, hy, ly);
                *(uint32_t*)&Ch[cOff + (size_t)(r + 8) * N + c] = pack2(hx, hy);
                *(uint32_t*)&Cl[cOff + (size_t)(r + 8) * N + c] = pack2(lx, ly);
            }
        }
    }
}

// ---------------------------------------------------------------------------
// Elementwise split: fp32 -> (hi, lo) bf16.  n % 1024 == 0.
// ---------------------------------------------------------------------------
__global__ __launch_bounds__(256)
void split_kernel(const float* __restrict__ in, __nv_bfloat16* __restrict__ h,
                  __nv_bfloat16* __restrict__ l, size_t n4)
{
    size_t i = (size_t)blockIdx.x * 256 + threadIdx.x;
    if (i >= n4) return;
    float4 v = ((const float4*)in)[i];
    __nv_bfloat16 hx, lx, hy, ly, hz, lz, hw, lw;
    split_bf16(v.x, hx, lx); split_bf16(v.y, hy, ly);
    split_bf16(v.z, hz, lz); split_bf16(v.w, hw, lw);
    uint2 uh, ul;
    uh.x = pack2(hx, hy); uh.y = pack2(hz, hw);
    ul.x = pack2(lx, ly); ul.y = pack2(lz, lw);
    *(uint2*)&h[i * 4] = uh;
    *(uint2*)&l[i * 4] = ul;
}

// ---------------------------------------------------------------------------
// Transpose + split (weights): fp32 in [rows][cols] -> (h,l) bf16 [cols][rows]
// ---------------------------------------------------------------------------
__global__ void transpose_split(const float* __restrict__ in,
                                __nv_bfloat16* __restrict__ h,
                                __nv_bfloat16* __restrict__ l,
                                int rows, int cols)
{
    __shared__ float t[32][33];
    int bx = blockIdx.x * 32, by = blockIdx.y * 32;
    int x = threadIdx.x, y = threadIdx.y;
    #pragma unroll
    for (int i = 0; i < 32; i += 8)
        t[y + i][x] = in[(size_t)(by + y + i) * cols + bx + x];
    __syncthreads();
    #pragma unroll
    for (int i = 0; i < 32; i += 8) {
        float v = t[x][y + i];
        __nv_bfloat16 hv, lv;
        split_bf16(v, hv, lv);
        size_t o = (size_t)(bx + y + i) * rows + by + x;
        h[o] = hv; l[o] = lv;
    }
}

// ---------------------------------------------------------------------------
// bf16 transpose (2-byte elements), batched over z.
// ---------------------------------------------------------------------------
__global__ void transpose16(const uint16_t* __restrict__ in,
                            uint16_t* __restrict__ outp, int rows, int cols)
{
    __shared__ uint16_t t[32][34];
    const size_t boff = (size_t)blockIdx.z * rows * cols;
    const uint16_t* ib = in + boff;
    uint16_t* ob = outp + boff;
    int bx = blockIdx.x * 32, by = blockIdx.y * 32;
    int x = threadIdx.x, y = threadIdx.y;
    #pragma unroll
    for (int i = 0; i < 32; i += 8)
        t[y + i][x] = ib[(size_t)(by + y + i) * cols + bx + x];
    __syncthreads();
    #pragma unroll
    for (int i = 0; i < 32; i += 8)
        ob[(size_t)(bx + y + i) * rows + by + x] = t[x][y + i];
}

// ---------------------------------------------------------------------------
// Row softmax over 2048 fp32 scores; writes split bf16 P.
// ---------------------------------------------------------------------------
__global__ __launch_bounds__(256)
void softmax_kernel(const float* __restrict__ S, __nv_bfloat16* __restrict__ Ph,
                    __nv_bfloat16* __restrict__ Pl)
{
    const float4* row = (const float4*)(S + (size_t)blockIdx.x * SEQ);
    __nv_bfloat16* ph = Ph + (size_t)blockIdx.x * SEQ;
    __nv_bfloat16* pl = Pl + (size_t)blockIdx.x * SEQ;
    const int tid = threadIdx.x;
    __shared__ float red[256];

    float4 v0 = row[tid];
    float4 v1 = row[tid + 256];

    float m = fmaxf(fmaxf(fmaxf(v0.x, v0.y), fmaxf(v0.z, v0.w)),
                    fmaxf(fmaxf(v1.x, v1.y), fmaxf(v1.z, v1.w)));
    red[tid] = m;
    __syncthreads();
    #pragma unroll
    for (int s = 128; s > 0; s >>= 1) {
        if (tid < s) red[tid] = fmaxf(red[tid], red[tid + s]);
        __syncthreads();
    }
    m = red[0];
    __syncthreads();

    v0.x = __expf(v0.x - m); v0.y = __expf(v0.y - m);
    v0.z = __expf(v0.z - m); v0.w = __expf(v0.w - m);
    v1.x = __expf(v1.x - m); v1.y = __expf(v1.y - m);
    v1.z = __expf(v1.z - m); v1.w = __expf(v1.w - m);

    float sum = (v0.x + v0.y + v0.z + v0.w) + (v1.x + v1.y + v1.z + v1.w);
    red[tid] = sum;
    __syncthreads();
    #pragma unroll
    for (int s = 128; s > 0; s >>= 1) {
        if (tid < s) red[tid] += red[tid + s];
        __syncthreads();
    }
    float inv = 1.0f / red[0];

    v0.x *= inv; v0.y *= inv; v0.z *= inv; v0.w *= inv;
    v1.x *= inv; v1.y *= inv; v1.z *= inv; v1.w *= inv;

    __nv_bfloat16 hx, lx, hy, ly, hz, lz, hw, lw;
    uint2 uh, ul;
    split_bf16(v0.x, hx, lx); split_bf16(v0.y, hy, ly);
    split_bf16(v0.z, hz, lz); split_bf16(v0.w, hw, lw);
    uh.x = pack2(hx, hy); uh.y = pack2(hz, hw);
    ul.x = pack2(lx, ly); ul.y = pack2(lz, lw);
    *(uint2*)&ph[tid * 4] = uh;
    *(uint2*)&pl[tid * 4] = ul;
    split_bf16(v1.x, hx, lx); split_bf16(v1.y, hy, ly);
    split_bf16(v1.z, hz, lz); split_bf16(v1.w, hw, lw);
    uh.x = pack2(hx, hy); uh.y = pack2(hz, hw);
    ul.x = pack2(lx, ly); ul.y = pack2(lz, lw);
    *(uint2*)&ph[(tid + 256) * 4] = uh;
    *(uint2*)&pl[(tid + 256) * 4] = ul;
}

// ---------------------------------------------------------------------------
// Host-side plumbing
// ---------------------------------------------------------------------------
extern "C" void kernel_launch(void* const* d_in, const int* in_sizes, int n_in,
                              void* d_out, int out_size)
{
    const float* x_a   = (const float*)d_in[0];
    const float* x_b   = (const float*)d_in[1];
    const float* sa_wq = (const float*)d_in[2];
    const float* sa_bq = (const float*)d_in[3];
    const float* sa_wk = (const float*)d_in[4];
    const float* sa_bk = (const float*)d_in[5];
    const float* sa_wv = (const float*)d_in[6];
    const float* sa_bv = (const float*)d_in[7];
    const float* sa_wo = (const float*)d_in[8];
    const float* sa_bo = (const float*)d_in[9];
    const float* ca_wq = (const float*)d_in[10];
    const float* ca_bq = (const float*)d_in[11];
    const float* ca_wk = (const float*)d_in[12];
    const float* ca_bk = (const float*)d_in[13];
    const float* ca_wv = (const float*)d_in[14];
    const float* ca_bv = (const float*)d_in[15];
    const float* ca_wo = (const float*)d_in[16];
    const float* ca_bo = (const float*)d_in[17];
    float* out = (float*)d_out;

    float *s, *xb2;
    __nv_bfloat16 *xbh, *xbl, *xah, *xal, *qh, *ql, *kh, *kl, *vh, *vl;
    __nv_bfloat16 *vth, *vtl, *ph, *pl, *x2h, *x2l, *ath, *atl, *wth, *wtl;
    cudaGetSymbolAddress((void**)&s,   g_s);
    cudaGetSymbolAddress((void**)&xb2, g_xb2);
    cudaGetSymbolAddress((void**)&xbh, g_xbh); cudaGetSymbolAddress((void**)&xbl, g_xbl);
    cudaGetSymbolAddress((void**)&xah, g_xah); cudaGetSymbolAddress((void**)&xal, g_xal);
    cudaGetSymbolAddress((void**)&qh,  g_qh);  cudaGetSymbolAddress((void**)&ql,  g_ql);
    cudaGetSymbolAddress((void**)&kh,  g_kh);  cudaGetSymbolAddress((void**)&kl,  g_kl);
    cudaGetSymbolAddress((void**)&vh,  g_vh);  cudaGetSymbolAddress((void**)&vl,  g_vl);
    cudaGetSymbolAddress((void**)&vth, g_vth); cudaGetSymbolAddress((void**)&vtl, g_vtl);
    cudaGetSymbolAddress((void**)&ph,  g_ph);  cudaGetSymbolAddress((void**)&pl,  g_pl);
    cudaGetSymbolAddress((void**)&x2h, g_x2h); cudaGetSymbolAddress((void**)&x2l, g_x2l);
    cudaGetSymbolAddress((void**)&ath, g_ath); cudaGetSymbolAddress((void**)&atl, g_atl);
    cudaGetSymbolAddress((void**)&wth, g_wth); cudaGetSymbolAddress((void**)&wtl, g_wtl);

    const int M = BATCH * SEQ;                  // 16384
    const size_t qkvS = (size_t)SEQ * DB;
    const size_t sS   = (size_t)SEQ * SEQ;
    const int WSZ = DB * DB;

    // ---- one-time operand prep -------------------------------------------
    {
        dim3 b(32, 8);
        dim3 gq(DB / 32, DB / 32);
        transpose_split<<<gq, b>>>(sa_wq, wth + 0 * WSZ, wtl + 0 * WSZ, DB, DB);
        transpose_split<<<gq, b>>>(sa_wk, wth + 1 * WSZ, wtl + 1 * WSZ, DB, DB);
        transpose_split<<<gq, b>>>(sa_wv, wth + 2 * WSZ, wtl + 2 * WSZ, DB, DB);
        transpose_split<<<gq, b>>>(sa_wo, wth + 3 * WSZ, wtl + 3 * WSZ, DB, DB);
        dim3 gc(DB / 32, DA / 32);
        transpose_split<<<gc, b>>>(ca_wq, wth + 4 * WSZ, wtl + 4 * WSZ, DA, DB);
        transpose_split<<<gq, b>>>(ca_wk, wth + 5 * WSZ, wtl + 5 * WSZ, DB, DB);
        transpose_split<<<gq, b>>>(ca_wv, wth + 6 * WSZ, wtl + 6 * WSZ, DB, DB);
        transpose_split<<<gq, b>>>(ca_wo, wth + 7 * WSZ, wtl + 7 * WSZ, DB, DB);
        size_t nb4 = (size_t)M * DB / 4, na4 = (size_t)M * DA / 4;
        split_kernel<<<(unsigned)((nb4 + 255) / 256), 256>>>(x_b, xbh, xbl, nb4);
        split_kernel<<<(unsigned)((na4 + 255) / 256), 256>>>(x_a, xah, xal, na4);
    }

    // ================= Self-attention on x_b ===============================
    {   // q,k,v projections: split output + bias
        dim3 g(DB / 128, M / 128, 1);
        mma_gemm<true, false, false, true><<<g, 256>>>(
            xbh, xbl, wth + 0 * WSZ, wtl + 0 * WSZ, sa_bq, nullptr,
            nullptr, qh, ql, M, DB, DB, 1.0f, 0, 0, 0);
        mma_gemm<true, false, false, true><<<g, 256>>>(
            xbh, xbl, wth + 1 * WSZ, wtl + 1 * WSZ, sa_bk, nullptr,
            nullptr, kh, kl, M, DB, DB, 1.0f, 0, 0, 0);
        mma_gemm<true, false, false, true><<<g, 256>>>(
            xbh, xbl, wth + 2 * WSZ, wtl + 2 * WSZ, sa_bv, nullptr,
            nullptr, vh, vl, M, DB, DB, 1.0f, 0, 0, 0);
    }
    {   // scores = Q @ K^T / 32 -> fp32
        dim3 g(SEQ / 128, SEQ / 128, BATCH);
        mma_gemm<false, false, true, false><<<g, 256>>>(
            qh, ql, kh, kl, nullptr, nullptr, s, nullptr, nullptr,
            SEQ, SEQ, DB, 1.0f / 32.0f, qkvS, qkvS, sS);
    }
    softmax_kernel<<<BATCH * SEQ, 256>>>(s, ph, pl);
    {   // V^T per batch (bf16 x2)
        dim3 b(32, 8), g(DB / 32, SEQ / 32, BATCH);
        transpose16<<<g, b>>>((const uint16_t*)vh, (uint16_t*)vth, SEQ, DB);
        transpose16<<<g, b>>>((const uint16_t*)vl, (uint16_t*)vtl, SEQ, DB);
    }
    {   // attn = P @ V -> split
        dim3 g(DB / 128, SEQ / 128, BATCH);
        mma_gemm<false, false, false, true><<<g, 256>>>(
            ph, pl, vth, vtl, nullptr, nullptr, nullptr, ath, atl,
            SEQ, DB, SEQ, 1.0f, sS, qkvS, qkvS);
    }
    {   // xb2 = x_b + attn @ Wo + bo  -> fp32 + split
        dim3 g(DB / 128, M / 128, 1);
        mma_gemm<true, true, true, true><<<g, 256>>>(
            ath, atl, wth + 3 * WSZ, wtl + 3 * WSZ, sa_bo, x_b,
            xb2, x2h, x2l, M, DB, DB, 1.0f, 0, 0, 0);
    }

    // ================= Cross-attention =====================================
    {
        dim3 g(DB / 128, M / 128, 1);
        mma_gemm<true, false, false, true><<<g, 256>>>(
            xah, xal, wth + 4 * WSZ, wtl + 4 * WSZ, ca_bq, nullptr,
            nullptr, qh, ql, M, DB, DA, 1.0f, 0, 0, 0);
        mma_gemm<true, false, false, true><<<g, 256>>>(
            x2h, x2l, wth + 5 * WSZ, wtl + 5 * WSZ, ca_bk, nullptr,
            nullptr, kh, kl, M, DB, DB, 1.0f, 0, 0, 0);
        mma_gemm<true, false, false, true><<<g, 256>>>(
            x2h, x2l, wth + 6 * WSZ, wtl + 6 * WSZ, ca_bv, nullptr,
            nullptr, vh, vl, M, DB, DB, 1.0f, 0, 0, 0);
    }
    {   // scores = Q @ K^T / sqrt(768)
        dim3 g(SEQ / 128, SEQ / 128, BATCH);
        mma_gemm<false, false, true, false><<<g, 256>>>(
            qh, ql, kh, kl, nullptr, nullptr, s, nullptr, nullptr,
            SEQ, SEQ, DB, 1.0f / sqrtf((float)DA), qkvS, qkvS, sS);
    }
    softmax_kernel<<<BATCH * SEQ, 256>>>(s, ph, pl);
    {
        dim3 b(32, 8), g(DB / 32, SEQ / 32, BATCH);
        transpose16<<<g, b>>>((const uint16_t*)vh, (uint16_t*)vth, SEQ, DB);
        transpose16<<<g, b>>>((const uint16_t*)vl, (uint16_t*)vtl, SEQ, DB);
    }
    {
        dim3 g(DB / 128, SEQ / 128, BATCH);
        mma_gemm<false, false, false, true><<<g, 256>>>(
            ph, pl, vth, vtl, nullptr, nullptr, nullptr, ath, atl,
            SEQ, DB, SEQ, 1.0f, sS, qkvS, qkvS);
    }
    {   // out = xb2 + attn @ Wo + bo -> fp32 only
        dim3 g(DB / 128, M / 128, 1);
        mma_gemm<true, true, true, false><<<g, 256>>>(
            ath, atl, wth + 7 * WSZ, wtl + 7 * WSZ, ca_bo, xb2,
            out, nullptr, nullptr, M, DB, DB, 1.0f, 0, 0, 0);
    }
}